// round 11
// baseline (speedup 1.0000x reference)
#include <cuda_runtime.h>
#include <math.h>
#include <stdint.h>

// Problem constants (fixed shapes)
#define Bc   2
#define Nn   8192
#define Ff   128
#define Ee   131072
#define Hh   256
#define NHh  4
#define Dd   64
#define FEATN 268
#define FEATP 288          // padded K for GEMM1
#define BE   (Bc*Ee)       // 262144 edge rows
#define BNr  (Bc*Nn)       // 16384 node rows

// ---------------- static scratch ----------------
static __device__ float g_ef[(size_t)BE * Hh];     // raw (pre-LN) edge features
static __device__ float g_stats[(size_t)BE * 2];   // per row: sum, sumsq (atomic-accumulated)
static __device__ float g_geo[(size_t)BE * 32];
static __device__ float g_cdiff[BE * 3];
static __device__ float g_wsc[BE];
static __device__ float g_agg[BNr * Hh];
static __device__ float g_nodemid[BNr * Hh];
// pre-transposed, pre-tf32 weights: BT[n][k]
static __device__ uint32_t g_w1T[Hh * FEATP];
static __device__ uint32_t g_w2T[2 * 128 * 128];
static __device__ uint32_t g_cw1T[Hh * Hh];
static __device__ uint32_t g_nw1T[Hh * (Hh + Ff)];
static __device__ uint32_t g_nw2T[Ff * Hh];

// ---------------- helpers ----------------
__device__ __forceinline__ uint32_t f2tf(float x) {
    uint32_t r; asm("cvt.rna.tf32.f32 %0, %1;" : "=r"(r) : "f"(x)); return r;
}
__device__ __forceinline__ void ldsm4(uint32_t& r0, uint32_t& r1, uint32_t& r2, uint32_t& r3, uint32_t a) {
    asm volatile("ldmatrix.sync.aligned.m8n8.x4.shared.b16 {%0,%1,%2,%3}, [%4];"
                 : "=r"(r0), "=r"(r1), "=r"(r2), "=r"(r3) : "r"(a));
}
__device__ __forceinline__ void mma8(float* c, const uint32_t* a, const uint32_t* b) {
    asm volatile("mma.sync.aligned.m16n8k8.row.col.f32.tf32.tf32.f32 "
                 "{%0,%1,%2,%3}, {%4,%5,%6,%7}, {%8,%9}, {%0,%1,%2,%3};"
                 : "+f"(c[0]), "+f"(c[1]), "+f"(c[2]), "+f"(c[3])
                 : "r"(a[0]), "r"(a[1]), "r"(a[2]), "r"(a[3]), "r"(b[0]), "r"(b[1]));
}
__device__ __forceinline__ float silu_f(float x) { return x / (1.f + expf(-x)); }
__device__ __forceinline__ void red4(float* addr, float4 v) {
    asm volatile("red.global.add.v4.f32 [%0], {%1,%2,%3,%4};"
                 :: "l"(addr), "f"(v.x), "f"(v.y), "f"(v.z), "f"(v.w) : "memory");
}

// ---------------- combined init ----------------
__global__ void k_misc(const float* __restrict__ coord, float* __restrict__ outc,
                       const float* __restrict__ w1, const float* __restrict__ w2,
                       const float* __restrict__ cw1, const float* __restrict__ nw1,
                       const float* __restrict__ nw2) {
    int idx = blockIdx.x * blockDim.x + threadIdx.x;
    if (idx < BNr * Hh) g_agg[idx] = 0.f;
    if (idx < BE) g_wsc[idx] = 0.f;
    if (idx < BE * 2) g_stats[idx] = 0.f;
    if (idx < Bc * Nn * 3) outc[idx] = coord[idx];
    if (idx < Hh * FEATP) {
        int n = idx / FEATP, f = idx - n * FEATP;
        g_w1T[idx] = (f < FEATN) ? f2tf(w1[(((n >> 6) * FEATN) + f) * Dd + (n & 63)]) : 0u;
    }
    if (idx < 2 * 128 * 128) {
        int p = idx >> 14, n = (idx >> 7) & 127, k = idx & 127;
        g_w2T[idx] = ((k >> 6) == (n >> 6))
            ? f2tf(w2[((p << 1) + (n >> 6)) * (Dd * Dd) + (k & 63) * Dd + (n & 63)]) : 0u;
    }
    if (idx < Hh * Hh) {
        int n = idx >> 8, k = idx & 255;
        g_cw1T[idx] = f2tf(cw1[k * Hh + n]);
    }
    if (idx < Hh * (Hh + Ff)) {
        int n = idx / (Hh + Ff), k = idx - n * (Hh + Ff);
        g_nw1T[idx] = f2tf(nw1[k * Hh + n]);
    }
    if (idx < Ff * Hh) {
        int n = idx >> 8, k = idx & 255;
        g_nw2T[idx] = f2tf(nw2[k * Ff + n]);
    }
}

// geometry features per edge (thread per edge)
__global__ void k_geo(const float* __restrict__ coord, const int* __restrict__ ei) {
    int e = blockIdx.x * blockDim.x + threadIdx.x;
    if (e >= BE) return;
    int b = (e >= Ee) ? 1 : 0, j = e - b * Ee;
    int i = ei[j], k = ei[Ee + j];
    const float* ci = coord + ((size_t)b * Nn + i) * 3;
    const float* ck = coord + ((size_t)b * Nn + k) * 3;
    float cix = ci[0], ciy = ci[1], ciz = ci[2];
    float ckx = ck[0], cky = ck[1], ckz = ck[2];
    float dx = cix - ckx, dy = ciy - cky, dz = ciz - ckz;
    float radial = dx * dx + dy * dy + dz * dz;
    float dist = sqrtf(radial);
    float dotv = cix * ckx + ciy * cky + ciz * ckz;
    float inva = 1.f / (dist + 1e-8f);
    float ax = dx * inva, ay = dy * inva, az = dz * inva;
    float crx = ciy * ckz - ciz * cky;
    float cry = ciz * ckx - cix * ckz;
    float crz = cix * cky - ciy * ckx;
    float nb = sqrtf(crx * crx + cry * cry + crz * crz);
    float invb = 1.f / (nb + 1e-8f);
    float bx = crx * invb, by = cry * invb, bz = crz * invb;
    float cx = ay * bz - az * by;
    float cy = az * bx - ax * bz;
    float cz = ax * by - ay * bx;
    float na  = sqrtf(ax * ax + ay * ay + az * az);
    float nbv = sqrtf(bx * bx + by * by + bz * bz);
    float ncv = sqrtf(cx * cx + cy * cy + cz * cz);
    bool bad = (na < 1e-6f) || (nbv < 1e-6f) || (ncv < 1e-6f);
    if (bad) { ax = 1.f; bx = 0.f; cx = 0.f;
               ay = 0.f; by = 1.f; cy = 0.f;
               az = 0.f; bz = 0.f; cz = 1.f; }
    float4* g = (float4*)(g_geo + (size_t)e * 32);
    g[0] = make_float4(radial, dist, dotv, ax);
    g[1] = make_float4(bx, cx, ay, by);
    g[2] = make_float4(cy, az, bz, cz);
    float4 z = make_float4(0.f, 0.f, 0.f, 0.f);
    g[3] = z; g[4] = z; g[5] = z; g[6] = z; g[7] = z;
    g_cdiff[e * 3 + 0] = dx;
    g_cdiff[e * 3 + 1] = dy;
    g_cdiff[e * 3 + 2] = dz;
}

// ---------------- tf32 tensor-core GEMM (double-buffered smem) ----------------
// Block tile 128x128, BK=32, 8 warps (2x4), warp tile 64x32.
// EPI: 2 bias+silu, 3 bias+residual, 4 bias+silu+dot(extra)->atomic wsc (no store)
// MODE: 0 normal A, 2 node-split A (h 128 | agg 256),
//       3 A with inline LayerNorm (stats/gam/bet) + fused agg segment-sum (bx==0 only)
#define AST 36
#define BST 36
#define MST 132
#define GT_BUF (128 * (AST + BST))
#define GT_SMEM (2 * GT_BUF * 4)

template <int EPI, int MODE>
__global__ void __launch_bounds__(256, 2) k_gemm_t(
    const float* __restrict__ A, const float* __restrict__ A2,
    const uint32_t* __restrict__ BT, float* __restrict__ C,
    int K, int lda, int ldbT, int ldc,
    const float* __restrict__ bias, const float* __restrict__ extra, int ldr,
    float* __restrict__ wsc, const float* __restrict__ stats,
    const float* __restrict__ gam, const float* __restrict__ bet,
    const int* __restrict__ ei, float* __restrict__ agg)
{
    extern __shared__ uint32_t smbuf[];
    const int tid = threadIdx.x, lane = tid & 31, wid = tid >> 5;
    const int wm = wid >> 2, wn = wid & 3;
    const int m0 = blockIdx.y * 128, n0 = blockIdx.x * 128;

    const int am = tid >> 3;
    const int ak = (tid & 7) << 2;

    const uint32_t* BTg = BT + (size_t)n0 * ldbT;

    const float* pA[4]; const float* pS[4];
    float mu_r[4], rs_r[4];
    int aggoff[4];
    const bool do_red = (MODE == 3) && (blockIdx.x == 0);
#pragma unroll
    for (int i = 0; i < 4; i++) {
        int r = m0 + am + 32 * i;
        if (MODE == 2) {
            pA[i] = A + (size_t)r * 128;
            pS[i] = A2 + (size_t)r * 256;
        } else {
            pA[i] = A + (size_t)r * lda;
        }
        if (MODE == 3) {
            float2 st = *(const float2*)(stats + 2 * (size_t)r);
            float mu = st.x * (1.f / 256.f);
            float var = st.y * (1.f / 256.f) - mu * mu;
            mu_r[i] = mu;
            rs_r[i] = rsqrtf(var + 1e-5f);
            int b = (r >= Ee) ? 1 : 0;
            aggoff[i] = (b * Nn + ei[r - b * Ee]) * Hh;
        }
    }
    auto loadA = [&](int i, int kcol) -> float4 {
        if (MODE == 2) {
            if (kcol < 128) return *(const float4*)(pA[i] + kcol);
            return *(const float4*)(pS[i] + (kcol - 128));
        }
        return *(const float4*)(pA[i] + kcol);
    };

    float acc[4][4][4];
#pragma unroll
    for (int i = 0; i < 4; i++)
#pragma unroll
        for (int j = 0; j < 4; j++) { acc[i][j][0] = 0.f; acc[i][j][1] = 0.f; acc[i][j][2] = 0.f; acc[i][j][3] = 0.f; }

    float4 pa[4]; uint4 pb[4];
#pragma unroll
    for (int i = 0; i < 4; i++) {
        pa[i] = loadA(i, ak);
        pb[i] = *(const uint4*)(BTg + (size_t)(am + 32 * i) * ldbT + ak);
    }

    const uint32_t as_base = (uint32_t)__cvta_generic_to_shared(smbuf);
    const uint32_t bs_base = as_base + 128 * AST * 4;
    const int a_r = wm * 64 + (lane & 15);
    const int a_q = (lane >> 4) << 2;
    const int b_r = wn * 32 + (lane & 7) + ((lane >> 4) << 3);
    const int b_q = ((lane >> 3) & 1) << 2;

    auto storeTiles = [&](int p, int kbase) {
        uint32_t* Ab = smbuf + p * GT_BUF;
        uint32_t* Bb = Ab + 128 * AST;
        float4 gm4, bt4;
        if (MODE == 3) {
            gm4 = *(const float4*)(gam + kbase + ak);
            bt4 = *(const float4*)(bet + kbase + ak);
        }
#pragma unroll
        for (int i = 0; i < 4; i++) {
            float4 v = pa[i];
            if (MODE == 3) {
                v.x = (v.x - mu_r[i]) * rs_r[i] * gm4.x + bt4.x;
                v.y = (v.y - mu_r[i]) * rs_r[i] * gm4.y + bt4.y;
                v.z = (v.z - mu_r[i]) * rs_r[i] * gm4.z + bt4.z;
                v.w = (v.w - mu_r[i]) * rs_r[i] * gm4.w + bt4.w;
                if (do_red) red4(agg + aggoff[i] + kbase + ak, v);
            }
            *(uint4*)&Ab[(am + 32 * i) * AST + ak] =
                make_uint4(f2tf(v.x), f2tf(v.y), f2tf(v.z), f2tf(v.w));
            *(uint4*)&Bb[(am + 32 * i) * BST + ak] = pb[i];
        }
    };

    storeTiles(0, 0);
    __syncthreads();

    int p = 0;
    for (int k0 = 0; k0 < K; k0 += 32) {
        bool more = (k0 + 32 < K);
        if (more) {
#pragma unroll
            for (int i = 0; i < 4; i++) {
                pa[i] = loadA(i, k0 + 32 + ak);
                pb[i] = *(const uint4*)(BTg + (size_t)(am + 32 * i) * ldbT + k0 + 32 + ak);
            }
        }
        const uint32_t ab = as_base + p * (GT_BUF * 4);
        const uint32_t bb = bs_base + p * (GT_BUF * 4);
#pragma unroll
        for (int kk = 0; kk < 4; kk++) {
            uint32_t af[4][4], bf[4][2];
#pragma unroll
            for (int mi = 0; mi < 4; mi++)
                ldsm4(af[mi][0], af[mi][1], af[mi][2], af[mi][3],
                      ab + (((a_r + mi * 16) * AST + kk * 8 + a_q) << 2));
#pragma unroll
            for (int np = 0; np < 2; np++) {
                uint32_t r0, r1, r2, r3;
                ldsm4(r0, r1, r2, r3,
                      bb + (((b_r + np * 16) * BST + kk * 8 + b_q) << 2));
                bf[np * 2][0] = r0; bf[np * 2][1] = r1;
                bf[np * 2 + 1][0] = r2; bf[np * 2 + 1][1] = r3;
            }
#pragma unroll
            for (int mi = 0; mi < 4; mi++)
#pragma unroll
                for (int ni = 0; ni < 4; ni++)
                    mma8(acc[mi][ni], af[mi], bf[ni]);
        }
        if (more) storeTiles(p ^ 1, k0 + 32);
        __syncthreads();
        p ^= 1;
    }

    // ---------------- epilogue ----------------
    const int row0 = m0 + wm * 64 + (lane >> 2);
    const int colw = wn * 32 + ((lane & 3) << 1);
#pragma unroll
    for (int mi = 0; mi < 4; mi++) {
        float slo = 0.f, shi = 0.f;
        int r = row0 + mi * 16;
#pragma unroll
        for (int ni = 0; ni < 4; ni++) {
            int col = n0 + colw + ni * 8;
            float2 bb = *(const float2*)(bias + col);
            float v0 = acc[mi][ni][0] + bb.x, v1 = acc[mi][ni][1] + bb.y;
            float v2 = acc[mi][ni][2] + bb.x, v3 = acc[mi][ni][3] + bb.y;
            if (EPI == 2 || EPI == 4) {
                v0 = silu_f(v0); v1 = silu_f(v1); v2 = silu_f(v2); v3 = silu_f(v3);
            }
            if (EPI == 3) {
                float2 ra = *(const float2*)(extra + (size_t)r * ldr + col);
                float2 rb = *(const float2*)(extra + (size_t)(r + 8) * ldr + col);
                v0 += ra.x; v1 += ra.y; v2 += rb.x; v3 += rb.y;
            }
            if (EPI == 4) {
                float2 w = *(const float2*)(extra + col);
                slo += v0 * w.x + v1 * w.y;
                shi += v2 * w.x + v3 * w.y;
            } else {
                *(float2*)(C + (size_t)r * ldc + col)       = make_float2(v0, v1);
                *(float2*)(C + (size_t)(r + 8) * ldc + col) = make_float2(v2, v3);
            }
        }
        if (EPI == 4) {
            slo += __shfl_xor_sync(0xffffffffu, slo, 1);
            slo += __shfl_xor_sync(0xffffffffu, slo, 2);
            shi += __shfl_xor_sync(0xffffffffu, shi, 1);
            shi += __shfl_xor_sync(0xffffffffu, shi, 2);
            if ((lane & 3) == 0) {
                atomicAdd(wsc + r, slo);
                atomicAdd(wsc + r + 8, shi);
            }
        }
    }
}

// ---------------- fused GEMM1+GEMM2 (double-buffered, +LN stats via atomics) ----------------
#define AB_BUF (128 * (AST + BST))

__global__ void __launch_bounds__(256) k_gemm12(
    const float* __restrict__ h, const uint32_t* __restrict__ w1T,
    const uint32_t* __restrict__ w2T, float* __restrict__ ef,
    const int* __restrict__ ei, const float* __restrict__ geo,
    const float* __restrict__ b1, const float* __restrict__ b2,
    float* __restrict__ stats)
{
    extern __shared__ uint32_t sm[];
    uint32_t* Ms = sm + 2 * AB_BUF;
    const int tid = threadIdx.x, lane = tid & 31, wid = tid >> 5;
    const int wm = wid >> 2, wn = wid & 3;
    const int m0 = blockIdx.y * 128, n0 = blockIdx.x * 128;

    const int am = tid >> 3;
    const int ak = (tid & 7) << 2;

    const uint32_t* BTg = w1T + (size_t)n0 * FEATP;

    const float* pA[4]; const float* pS[4]; const float* pG[4];
    {
        int b = (m0 >= Ee) ? 1 : 0;
#pragma unroll
        for (int i = 0; i < 4; i++) {
            int r = m0 + am + 32 * i;
            int j = r - b * Ee;
            pA[i] = h + ((size_t)b * Nn + ei[j]) * Ff;
            pS[i] = h + ((size_t)b * Nn + ei[Ee + j]) * Ff;
            pG[i] = geo + (size_t)r * 32;
        }
    }
    auto loadA = [&](int i, int kcol) -> float4 {
        if (kcol < 128) return *(const float4*)(pA[i] + kcol);
        if (kcol < 256) return *(const float4*)(pS[i] + (kcol - 128));
        return *(const float4*)(pG[i] + (kcol - 256));
    };

    float acc[4][4][4];
#pragma unroll
    for (int i = 0; i < 4; i++)
#pragma unroll
        for (int j = 0; j < 4; j++) { acc[i][j][0] = 0.f; acc[i][j][1] = 0.f; acc[i][j][2] = 0.f; acc[i][j][3] = 0.f; }

    float4 pa[4]; uint4 pb[4];
#pragma unroll
    for (int i = 0; i < 4; i++) {
        pa[i] = loadA(i, ak);
        pb[i] = *(const uint4*)(BTg + (size_t)(am + 32 * i) * FEATP + ak);
    }

    const uint32_t as_base = (uint32_t)__cvta_generic_to_shared(sm);
    const uint32_t bs_base = as_base + 128 * AST * 4;
    const uint32_t ms_base = as_base + 2 * AB_BUF * 4;
    const int a_r = wm * 64 + (lane & 15);
    const int a_q = (lane >> 4) << 2;
    const int b_r = wn * 32 + (lane & 7) + ((lane >> 4) << 3);
    const int b_q = ((lane >> 3) & 1) << 2;

    auto storeTiles = [&](int p) {
        uint32_t* Ab = sm + p * AB_BUF;
        uint32_t* Bb = Ab + 128 * AST;
#pragma unroll
        for (int i = 0; i < 4; i++) {
            *(uint4*)&Ab[(am + 32 * i) * AST + ak] =
                make_uint4(f2tf(pa[i].x), f2tf(pa[i].y), f2tf(pa[i].z), f2tf(pa[i].w));
            *(uint4*)&Bb[(am + 32 * i) * BST + ak] = pb[i];
        }
    };

    // ---- stage 1 mainloop, K=288, double-buffered ----
    storeTiles(0);
    __syncthreads();
    int p = 0;
    for (int k0 = 0; k0 < FEATP; k0 += 32) {
        bool more = (k0 + 32 < FEATP);
        if (more) {
#pragma unroll
            for (int i = 0; i < 4; i++) {
                pa[i] = loadA(i, k0 + 32 + ak);
                pb[i] = *(const uint4*)(BTg + (size_t)(am + 32 * i) * FEATP + k0 + 32 + ak);
            }
        }
        const uint32_t ab = as_base + p * (AB_BUF * 4);
        const uint32_t bb = bs_base + p * (AB_BUF * 4);
#pragma unroll
        for (int kk = 0; kk < 4; kk++) {
            uint32_t af[4][4], bf[4][2];
#pragma unroll
            for (int mi = 0; mi < 4; mi++)
                ldsm4(af[mi][0], af[mi][1], af[mi][2], af[mi][3],
                      ab + (((a_r + mi * 16) * AST + kk * 8 + a_q) << 2));
#pragma unroll
            for (int np = 0; np < 2; np++) {
                uint32_t r0, r1, r2, r3;
                ldsm4(r0, r1, r2, r3,
                      bb + (((b_r + np * 16) * BST + kk * 8 + b_q) << 2));
                bf[np * 2][0] = r0; bf[np * 2][1] = r1;
                bf[np * 2 + 1][0] = r2; bf[np * 2 + 1][1] = r3;
            }
#pragma unroll
            for (int mi = 0; mi < 4; mi++)
#pragma unroll
                for (int ni = 0; ni < 4; ni++)
                    mma8(acc[mi][ni], af[mi], bf[ni]);
        }
        if (more) storeTiles(p ^ 1);
        __syncthreads();
        p ^= 1;
    }

    // ---- epilogue 1: silu + bias -> Ms (tf32), reset acc ----
    const int lrow0 = wm * 64 + (lane >> 2);
    const int lcolw = wn * 32 + ((lane & 3) << 1);
#pragma unroll
    for (int mi = 0; mi < 4; mi++) {
        int r = lrow0 + mi * 16;
#pragma unroll
        for (int ni = 0; ni < 4; ni++) {
            int col = lcolw + ni * 8;
            float2 bb = *(const float2*)(b1 + n0 + col);
            float v0 = silu_f(acc[mi][ni][0] + bb.x);
            float v1 = silu_f(acc[mi][ni][1] + bb.y);
            float v2 = silu_f(acc[mi][ni][2] + bb.x);
            float v3 = silu_f(acc[mi][ni][3] + bb.y);
            *(uint2*)&Ms[r * MST + col]       = make_uint2(f2tf(v0), f2tf(v1));
            *(uint2*)&Ms[(r + 8) * MST + col] = make_uint2(f2tf(v2), f2tf(v3));
            acc[mi][ni][0] = 0.f; acc[mi][ni][1] = 0.f;
            acc[mi][ni][2] = 0.f; acc[mi][ni][3] = 0.f;
        }
    }

    // ---- stage 2 mainloop, K=128, A from Ms, B = w2 pair tile (double-buffered Bs) ----
    const uint32_t* W2 = w2T + (size_t)blockIdx.x * (128 * 128);
#pragma unroll
    for (int i = 0; i < 4; i++)
        pb[i] = *(const uint4*)(W2 + (size_t)(am + 32 * i) * 128 + ak);
    {
        uint32_t* Bb = sm + 128 * AST;   // buf0 Bs
#pragma unroll
        for (int i = 0; i < 4; i++)
            *(uint4*)&Bb[(am + 32 * i) * BST + ak] = pb[i];
    }
    __syncthreads();   // covers Ms writes + Bs0 store
    p = 0;
    for (int k0 = 0; k0 < 128; k0 += 32) {
        bool more = (k0 + 32 < 128);
        if (more) {
#pragma unroll
            for (int i = 0; i < 4; i++)
                pb[i] = *(const uint4*)(W2 + (size_t)(am + 32 * i) * 128 + k0 + 32 + ak);
        }
        const uint32_t bb = bs_base + p * (AB_BUF * 4);
#pragma unroll
        for (int kk = 0; kk < 4; kk++) {
            uint32_t af[4][4], bf[4][2];
#pragma unroll
            for (int mi = 0; mi < 4; mi++)
                ldsm4(af[mi][0], af[mi][1], af[mi][2], af[mi][3],
                      ms_base + (((a_r + mi * 16) * MST + k0 + kk * 8 + a_q) << 2));
#pragma unroll
            for (int np = 0; np < 2; np++) {
                uint32_t r0, r1, r2, r3;
                ldsm4(r0, r1, r2, r3,
                      bb + (((b_r + np * 16) * BST + kk * 8 + b_q) << 2));
                bf[np * 2][0] = r0; bf[np * 2][1] = r1;
                bf[np * 2 + 1][0] = r2; bf[np * 2 + 1][1] = r3;
            }
#pragma unroll
            for (int mi = 0; mi < 4; mi++)
#pragma unroll
                for (int ni = 0; ni < 4; ni++)
                    mma8(acc[mi][ni], af[mi], bf[ni]);
        }
        if (more) {
            uint32_t* Bb = sm + (p ^ 1) * AB_BUF + 128 * AST;
#pragma unroll
            for (int i = 0; i < 4; i++)
                *(uint4*)&Bb[(am + 32 * i) * BST + ak] = pb[i];
        }
        __syncthreads();
        p ^= 1;
    }

    // ---- epilogue 2: + b2, store f32 to ef, LN partial stats via atomics ----
#pragma unroll
    for (int mi = 0; mi < 4; mi++) {
        int r = m0 + lrow0 + mi * 16;
        float s_lo = 0.f, ss_lo = 0.f, s_hi = 0.f, ss_hi = 0.f;
#pragma unroll
        for (int ni = 0; ni < 4; ni++) {
            int col = n0 + lcolw + ni * 8;
            float2 bb = *(const float2*)(b2 + col);
            float v0 = acc[mi][ni][0] + bb.x, v1 = acc[mi][ni][1] + bb.y;
            float v2 = acc[mi][ni][2] + bb.x, v3 = acc[mi][ni][3] + bb.y;
            *(float2*)(ef + (size_t)r * Hh + col)       = make_float2(v0, v1);
            *(float2*)(ef + (size_t)(r + 8) * Hh + col) = make_float2(v2, v3);
            s_lo += v0 + v1; ss_lo += v0 * v0 + v1 * v1;
            s_hi += v2 + v3; ss_hi += v2 * v2 + v3 * v3;
        }
        s_lo  += __shfl_xor_sync(0xffffffffu, s_lo, 1);
        s_lo  += __shfl_xor_sync(0xffffffffu, s_lo, 2);
        ss_lo += __shfl_xor_sync(0xffffffffu, ss_lo, 1);
        ss_lo += __shfl_xor_sync(0xffffffffu, ss_lo, 2);
        s_hi  += __shfl_xor_sync(0xffffffffu, s_hi, 1);
        s_hi  += __shfl_xor_sync(0xffffffffu, s_hi, 2);
        ss_hi += __shfl_xor_sync(0xffffffffu, ss_hi, 1);
        ss_hi += __shfl_xor_sync(0xffffffffu, ss_hi, 2);
        if ((lane & 3) == 0) {
            atomicAdd(stats + 2 * (size_t)r,           s_lo);
            atomicAdd(stats + 2 * (size_t)r + 1,       ss_lo);
            atomicAdd(stats + 2 * (size_t)(r + 8),     s_hi);
            atomicAdd(stats + 2 * (size_t)(r + 8) + 1, ss_hi);
        }
    }
}

// coord scatter: thread per edge
__global__ void k_coordscatter(const int* __restrict__ ei, float* __restrict__ outc) {
    int e = blockIdx.x * blockDim.x + threadIdx.x;
    if (e >= BE) return;
    int b = (e >= Ee) ? 1 : 0, j = e - b * Ee;
    int i = ei[j];
    float wv = g_wsc[e];
    float* dst = outc + ((size_t)b * Nn + i) * 3;
    atomicAdd(dst + 0, g_cdiff[e * 3 + 0] * wv);
    atomicAdd(dst + 1, g_cdiff[e * 3 + 1] * wv);
    atomicAdd(dst + 2, g_cdiff[e * 3 + 2] * wv);
}

// ---------------- launch ----------------
extern "C" void kernel_launch(void* const* d_in, const int* in_sizes, int n_in,
                              void* d_out, int out_size) {
    const float* h     = (const float*)d_in[0];
    const float* coord = (const float*)d_in[1];
    const int*   ei    = (const int*)d_in[2];
    const float* ew1   = (const float*)d_in[3];
    const float* eb1   = (const float*)d_in[4];
    const float* ew2   = (const float*)d_in[5];
    const float* eb2   = (const float*)d_in[6];
    const float* lng   = (const float*)d_in[7];
    const float* lnb   = (const float*)d_in[8];
    const float* nw1   = (const float*)d_in[9];
    const float* nb1   = (const float*)d_in[10];
    const float* nw2   = (const float*)d_in[11];
    const float* nb2   = (const float*)d_in[12];
    const float* cw1   = (const float*)d_in[13];
    const float* cb1   = (const float*)d_in[14];
    const float* cw2   = (const float*)d_in[15];

    float* out_h = (float*)d_out;
    float* out_c = out_h + (size_t)BNr * Ff;

    void *p_ef, *p_stats, *p_geo, *p_w1T, *p_w2T, *p_cw1T, *p_nw1T, *p_nw2T,
         *p_agg, *p_nodemid, *p_wsc;
    cudaGetSymbolAddress(&p_ef,      g_ef);
    cudaGetSymbolAddress(&p_stats,   g_stats);
    cudaGetSymbolAddress(&p_geo,     g_geo);
    cudaGetSymbolAddress(&p_w1T,     g_w1T);
    cudaGetSymbolAddress(&p_w2T,     g_w2T);
    cudaGetSymbolAddress(&p_cw1T,    g_cw1T);
    cudaGetSymbolAddress(&p_nw1T,    g_nw1T);
    cudaGetSymbolAddress(&p_nw2T,    g_nw2T);
    cudaGetSymbolAddress(&p_agg,     g_agg);
    cudaGetSymbolAddress(&p_nodemid, g_nodemid);
    cudaGetSymbolAddress(&p_wsc,     g_wsc);
    float*          efp      = (float*)p_ef;
    float*          statsp   = (float*)p_stats;
    const float*    geop     = (const float*)p_geo;
    const uint32_t* w1Tp     = (const uint32_t*)p_w1T;
    const uint32_t* w2Tp     = (const uint32_t*)p_w2T;
    const uint32_t* cw1Tp    = (const uint32_t*)p_cw1T;
    const uint32_t* nw1Tp    = (const uint32_t*)p_nw1T;
    const uint32_t* nw2Tp    = (const uint32_t*)p_nw2T;
    float*          aggp     = (float*)p_agg;
    float*          nodemidp = (float*)p_nodemid;
    float*          wscp     = (float*)p_wsc;

    const int smem12 = (2 * AB_BUF + 128 * MST) * 4;   // ~138 KB
    cudaFuncSetAttribute(k_gemm12, cudaFuncAttributeMaxDynamicSharedMemorySize, smem12);
    cudaFuncSetAttribute(k_gemm_t<4, 3>, cudaFuncAttributeMaxDynamicSharedMemorySize, GT_SMEM);
    cudaFuncSetAttribute(k_gemm_t<2, 2>, cudaFuncAttributeMaxDynamicSharedMemorySize, GT_SMEM);
    cudaFuncSetAttribute(k_gemm_t<3, 0>, cudaFuncAttributeMaxDynamicSharedMemorySize, GT_SMEM);

    // init + weights transform (also zeroes stats/agg/wsc)
    k_misc<<<(BNr * Hh + 255) / 256, 256>>>(coord, out_c, ew1, ew2, cw1, nw1, nw2);
    k_geo<<<BE / 256, 256>>>(coord, ei);

    // fused GEMM1+GEMM2 (+ atomic LN stats)
    k_gemm12<<<dim3(2, BE / 128), 256, smem12>>>(h, w1Tp, w2Tp, efp, ei, geop, eb1, eb2, statsp);

    // GEMM3 fused: wsc += silu(LN(ef) @ cw1 + cb1) . cw2
    //   + agg segment-sum fused into the A-load path (blockIdx.x==0 only)
    k_gemm_t<4, 3><<<dim3(2, BE / 128), 256, GT_SMEM>>>(
        efp, nullptr, cw1Tp, nullptr, Hh, Hh, Hh, 0, cb1, cw2, 0, wscp, statsp,
        lng, lnb, ei, aggp);

    // coord scatter
    k_coordscatter<<<BE / 256, 256>>>(ei, out_c);

    // node MLP (input concat fused via split-A)
    k_gemm_t<2, 2><<<dim3(2, BNr / 128), 256, GT_SMEM>>>(
        h, aggp, nw1Tp, nodemidp, Hh + Ff, 0, Hh + Ff, Hh, nb1, nullptr, 0, nullptr,
        nullptr, nullptr, nullptr, nullptr, nullptr);
    k_gemm_t<3, 0><<<dim3(1, BNr / 128), 256, GT_SMEM>>>(
        nodemidp, nullptr, nw2Tp, out_h, Hh, Hh, Hh, Ff, nb2, h, Ff, nullptr,
        nullptr, nullptr, nullptr, nullptr, nullptr);
}